// round 16
// baseline (speedup 1.0000x reference)
#include <cuda_runtime.h>
#include <cuda_bf16.h>
#include <cuda_fp8.h>
#include <math.h>
#include <stdint.h>

// Problem constants
#define BB    64
#define MAXT  511
#define TP1   512
#define SDIM  1024
#define HDIM  4096

// Tiling (fp8: KC = 128 k-elements = 128 bytes per row-chunk)
#define MT       128                  // rows per item
#define TILES_PER_B 4
#define KC       128
#define NCHUNK   (SDIM/KC)            // 8 chunks per item
#define NT       128                  // H cols per item
#define NNT      (HDIM/NT)            // 32
#define NITEMS   (NNT*BB*TILES_PER_B) // 8192 items: (nt, b, tile) nt-major
#define THREADS  256                  // 8 warps: 4 warp_m x 2 warp_n, each 32x64
#define GRID     296                  // persistent CTAs (2/SM)
#define NSTAGE   3

// SMEM layout (bytes)
#define A_OFF(s)  ((s)*16384)             // 3 x 16 KB (128 rows x 128B)
#define B_OFF(s)  (49152 + (s)*16384)     // 3 x 16 KB (128 rows x 128B)
#define LOG_OFF   98304                   // 128*4 floats = 2 KB
#define ITEM_OFF  100352
#define SMEM_BYTES 100480

#define SW128(x) ((x) ^ (((x) >> 3) & 0x70))

__device__ uint8_t g_sbf[(size_t)BB * TP1 * SDIM];   // 33.5 MB: s in e4m3
__device__ uint8_t g_w1t[(size_t)HDIM * SDIM];       // 4 MB  : W1^T e4m3
__device__ float   g_logits[(size_t)BB * TP1 * 4];   // 512 KB partial logits
__device__ float   g_post[BB];
__device__ unsigned g_counter;

// ---------------- helpers ----------------
__device__ __forceinline__ uint32_t smem_u32(const void* p) {
    uint32_t a;
    asm("{ .reg .u64 t; cvta.to.shared.u64 t, %1; cvt.u32.u64 %0, t; }" : "=r"(a) : "l"(p));
    return a;
}
__device__ __forceinline__ uint32_t fp8x4(float a, float b, float c, float d) {
    __nv_fp8x2_storage_t lo = __nv_cvt_float2_to_fp8x2(make_float2(a, b),
                                                       __NV_SATFINITE, __NV_E4M3);
    __nv_fp8x2_storage_t hi = __nv_cvt_float2_to_fp8x2(make_float2(c, d),
                                                       __NV_SATFINITE, __NV_E4M3);
    return (uint32_t)lo | ((uint32_t)hi << 16);
}
__device__ __forceinline__ void cp16(uint32_t dst, const void* src) {
    asm volatile("cp.async.cg.shared.global [%0], [%1], 16;" :: "r"(dst), "l"(src));
}
__device__ __forceinline__ void ldsm_x4(uint32_t* r, uint32_t addr) {
    asm volatile("ldmatrix.sync.aligned.m8n8.x4.shared.b16 {%0,%1,%2,%3}, [%4];"
                 : "=r"(r[0]), "=r"(r[1]), "=r"(r[2]), "=r"(r[3]) : "r"(addr));
}
__device__ __forceinline__ void mma16832(float* d, const uint32_t* a,
                                         uint32_t b0, uint32_t b1) {
    asm volatile("mma.sync.aligned.m16n8k32.row.col.f32.e4m3.e4m3.f32 "
                 "{%0,%1,%2,%3}, {%4,%5,%6,%7}, {%8,%9}, {%0,%1,%2,%3};"
                 : "+f"(d[0]), "+f"(d[1]), "+f"(d[2]), "+f"(d[3])
                 : "r"(a[0]), "r"(a[1]), "r"(a[2]), "r"(a[3]), "r"(b0), "r"(b1));
}

// ---------------- prepass kernels ----------------
extern "C" __global__ void init_counter() { g_counter = 0u; }

extern "C" __global__ void zero_logits() {
    ((float4*)g_logits)[blockIdx.x * 256 + threadIdx.x] = make_float4(0.f, 0.f, 0.f, 0.f);
}

extern "C" __global__ void s_cvt(const float* __restrict__ s) {
    size_t i = (size_t)blockIdx.x * 256 + threadIdx.x;
    const float4* p = (const float4*)s + i * 4;
    float4 v0 = p[0], v1 = p[1], v2 = p[2], v3 = p[3];
    uint4 o;
    o.x = fp8x4(v0.x, v0.y, v0.z, v0.w);
    o.y = fp8x4(v1.x, v1.y, v1.z, v1.w);
    o.z = fp8x4(v2.x, v2.y, v2.z, v2.w);
    o.w = fp8x4(v3.x, v3.y, v3.z, v3.w);
    ((uint4*)g_sbf)[i] = o;
}

extern "C" __global__ void w1_transpose(const float* __restrict__ W1) {
    __shared__ float tile[32][33];
    int n0 = blockIdx.x * 32, k0 = blockIdx.y * 32;
    int tx = threadIdx.x, ty = threadIdx.y;
    #pragma unroll
    for (int i = 0; i < 32; i += 8)
        tile[ty + i][tx] = W1[(size_t)(k0 + ty + i) * HDIM + n0 + tx];
    __syncthreads();
    #pragma unroll
    for (int i = 0; i < 32; i += 8) {
        __nv_fp8_storage_t v = __nv_cvt_float_to_fp8(tile[tx][ty + i],
                                                     __NV_SATFINITE, __NV_E4M3);
        g_w1t[(size_t)(n0 + ty + i) * SDIM + k0 + tx] = (uint8_t)v;
    }
}

// ---------------- main persistent kernel ----------------
extern "C" __global__ void __launch_bounds__(THREADS, 2)
traj_main(const int* __restrict__ lengths, const float* __restrict__ b1,
          const float* __restrict__ W2)
{
    extern __shared__ __align__(1024) char smem[];
    float*    logitsS = (float*)(smem + LOG_OFF);
    unsigned* itemS   = (unsigned*)(smem + ITEM_OFF);
    const uint32_t smem_u = smem_u32(smem);

    const int tid  = threadIdx.x;
    const int lane = tid & 31;
    const int wid  = tid >> 5;
    const int warp_m = wid & 3;          // 4 row-groups of 32 (128 rows)
    const int warp_n = wid >> 2;         // 2 col-groups of 64 (128 cols)
    const int m0  = warp_m * 32;
    const int n0w = warp_n * 64;

    // Per-thread cp.async base; per-piece strides are swizzle-transparent
    const int rowT = tid >> 3, kgT = tid & 7;       // rowT 0..31
    const int src0 = rowT * SDIM + kgT * 16;
    const uint32_t dst0 = SW128(rowT * 128 + kgT * 16);
    const uint32_t offA0 = SW128((m0 + (lane & 15)) * 128 + (lane >> 4) * 16);
    const uint32_t offB0 = SW128((n0w + (lane & 15)) * 128 + (lane >> 4) * 16);

    for (;;) {
        if (tid == 0) itemS[0] = atomicAdd(&g_counter, 1u);
        __syncthreads();
        const unsigned item = itemS[0];
        __syncthreads();
        if (item >= NITEMS) break;
        // nt in HIGH bits (R11-proven ordering)
        const int nt   = item >> 8;
        const int rem  = item & 255;
        const int b    = rem >> 2;
        const int tile = rem & 3;
        const int t_base = tile * MT;
        const int len = lengths[b];
        if (t_base >= len) continue;

        logitsS[tid] = 0.f;                // 128 rows x 4 actions = 512 floats
        logitsS[tid + 256] = 0.f;

        const uint8_t* abase = g_sbf + ((size_t)b * TP1 + t_base) * SDIM + src0;
        const uint8_t* bbase = g_w1t + (size_t)nt * NT * SDIM + src0;

        float d[2][8][4];
        #pragma unroll
        for (int mi = 0; mi < 2; ++mi)
            #pragma unroll
            for (int ni = 0; ni < 8; ++ni)
                #pragma unroll
                for (int k = 0; k < 4; ++k) d[mi][ni][k] = 0.f;

        // ---- preload chunks 0,1 into stages 0,1 (4 A + 4 B pieces/thread) ----
        #pragma unroll
        for (int pc = 0; pc < 2; ++pc) {
            #pragma unroll
            for (int i = 0; i < 4; ++i)
                cp16(smem_u + A_OFF(pc) + dst0 + i * 4096,
                     abase + pc * KC + i * 32 * SDIM);
            #pragma unroll
            for (int i = 0; i < 4; ++i)
                cp16(smem_u + B_OFF(pc) + dst0 + i * 4096,
                     bbase + pc * KC + i * 32 * SDIM);
            asm volatile("cp.async.commit_group;");
        }

        for (int c = 0; c < NCHUNK; ++c) {
            if (c < NCHUNK - 1) asm volatile("cp.async.wait_group 1;");
            else                asm volatile("cp.async.wait_group 0;");
            __syncthreads();               // single barrier per chunk

            const int st = c % 3;
            const uint32_t aS = smem_u + A_OFF(st);
            const uint32_t bS = smem_u + B_OFF(st);

            // fragment-pipelined ks loop: bq double-buffered 1 ks ahead
            uint32_t bq0[4][4], bq1[4][4];
            {
                const uint32_t bB = bS + offB0;
                #pragma unroll
                for (int nj = 0; nj < 4; ++nj)
                    ldsm_x4(bq0[nj], bB + nj * 2048);
            }
            #pragma unroll
            for (int ks = 0; ks < 4; ++ks) {
                const uint32_t kx = (uint32_t)(ks << 5);
                uint32_t afr[2][4];
                {
                    const uint32_t aB = aS + (offA0 ^ kx);
                    #pragma unroll
                    for (int mi = 0; mi < 2; ++mi)
                        ldsm_x4(afr[mi], aB + mi * 2048);
                }
                uint32_t (*cur)[4] = (ks & 1) ? bq1 : bq0;
                uint32_t (*nxt)[4] = (ks & 1) ? bq0 : bq1;
                if (ks < 3) {
                    const uint32_t bB = bS + (offB0 ^ (uint32_t)((ks + 1) << 5));
                    #pragma unroll
                    for (int nj = 0; nj < 4; ++nj)
                        ldsm_x4(nxt[nj], bB + nj * 2048);
                }
                #pragma unroll
                for (int mi = 0; mi < 2; ++mi)
                    #pragma unroll
                    for (int nj = 0; nj < 4; ++nj) {
                        mma16832(d[mi][2*nj],   afr[mi], cur[nj][0], cur[nj][2]);
                        mma16832(d[mi][2*nj+1], afr[mi], cur[nj][1], cur[nj][3]);
                    }
            }

            // prefetch chunk c+2 into stage (c+2)%3 == (c-1)%3: its readers
            // (chunk c-1) all passed this iteration's top barrier.
            if (c + 2 < NCHUNK) {
                const int ps = (c + 2) % 3;
                const int koff = (c + 2) * KC;
                #pragma unroll
                for (int i = 0; i < 4; ++i)
                    cp16(smem_u + A_OFF(ps) + dst0 + i * 4096,
                         abase + koff + i * 32 * SDIM);
                #pragma unroll
                for (int i = 0; i < 4; ++i)
                    cp16(smem_u + B_OFF(ps) + dst0 + i * 4096,
                         bbase + koff + i * 32 * SDIM);
                asm volatile("cp.async.commit_group;");
            }
        }

        // ---- fused epilogue: relu(acc+b1) . W2[:,0:4] ----
        float plog[4][4];
        #pragma unroll
        for (int i = 0; i < 4; ++i)
            #pragma unroll
            for (int a = 0; a < 4; ++a) plog[i][a] = 0.f;

        #pragma unroll
        for (int ni = 0; ni < 8; ++ni) {
            #pragma unroll
            for (int jc = 0; jc < 2; ++jc) {
                int col = nt * NT + n0w + ni * 8 + 2 * (lane & 3) + jc;
                float bias = __ldg(b1 + col);
                float4 w2v = *(const float4*)(W2 + (size_t)col * 32);
                #pragma unroll
                for (int mi = 0; mi < 2; ++mi) {
                    #pragma unroll
                    for (int half = 0; half < 2; ++half) {
                        float h = d[mi][ni][half * 2 + jc] + bias;
                        h = fmaxf(h, 0.f);
                        int slot = mi * 2 + half;
                        plog[slot][0] += h * w2v.x;
                        plog[slot][1] += h * w2v.y;
                        plog[slot][2] += h * w2v.z;
                        plog[slot][3] += h * w2v.w;
                    }
                }
            }
        }

        #pragma unroll
        for (int slot = 0; slot < 4; ++slot) {
            int row = m0 + (slot >> 1) * 16 + (slot & 1) * 8 + (lane >> 2);
            #pragma unroll
            for (int a = 0; a < 4; ++a)
                atomicAdd(&logitsS[row * 4 + a], plog[slot][a]);
        }
        __syncthreads();
        if (tid < MT) {
            float* gl = g_logits + ((size_t)b * TP1 + t_base + tid) * 4;
            #pragma unroll
            for (int a = 0; a < 4; ++a)
                atomicAdd(gl + a, logitsS[tid * 4 + a]);
        }
    }
}

// ---------------- post: softmax + gather + masked sum per batch ----------------
extern "C" __global__ void traj_post(const int* __restrict__ actions,
                                     const int* __restrict__ lengths,
                                     const float* __restrict__ b2)
{
    const int b = blockIdx.x;
    const int tid = threadIdx.x;
    const int len = lengths[b];
    const float bb0 = b2[0], bb1 = b2[1], bb2 = b2[2], bb3 = b2[3];
    float acc = 0.f;
    for (int t = tid; t < len; t += 256) {
        const float4 z4 = *(const float4*)(g_logits + ((size_t)b * TP1 + t) * 4);
        float z[4] = { z4.x + bb0, z4.y + bb1, z4.z + bb2, z4.w + bb3 };
        float zm = fmaxf(fmaxf(z[0], z[1]), fmaxf(z[2], z[3]));
        float se = expf(z[0]-zm) + expf(z[1]-zm) + expf(z[2]-zm) + expf(z[3]-zm);
        float lse = zm + logf(se);
        int act = actions[b * MAXT + t];
        acc += z[act] - lse;
    }
    #pragma unroll
    for (int off = 16; off > 0; off >>= 1)
        acc += __shfl_xor_sync(0xffffffffu, acc, off);
    __shared__ float red[8];
    if ((tid & 31) == 0) red[tid >> 5] = acc;
    __syncthreads();
    if (tid == 0) {
        float s = 0.f;
        #pragma unroll
        for (int w = 0; w < 8; ++w) s += red[w];
        g_post[b] = s;
    }
}

extern "C" __global__ void traj_reduce(float* __restrict__ out)
{
    __shared__ float sm[BB];
    int i = threadIdx.x;
    sm[i] = g_post[i];
    __syncthreads();
    for (int off = BB / 2; off > 0; off >>= 1) {
        if (i < off) sm[i] += sm[i + off];
        __syncthreads();
    }
    if (i == 0) out[0] = -sm[0];
}

extern "C" void kernel_launch(void* const* d_in, const int* in_sizes, int n_in,
                              void* d_out, int out_size)
{
    const float* s_in    = (const float*)d_in[0];
    const int*   actions = (const int*)  d_in[1];
    const int*   lengths = (const int*)  d_in[2];
    const float* W1      = (const float*)d_in[3];
    const float* b1      = (const float*)d_in[4];
    const float* W2      = (const float*)d_in[5];
    const float* b2      = (const float*)d_in[6];
    float* out = (float*)d_out;

    cudaFuncSetAttribute(traj_main, cudaFuncAttributeMaxDynamicSharedMemorySize, SMEM_BYTES);

    init_counter<<<1, 1>>>();
    zero_logits<<<512, 256>>>();
    s_cvt<<<(BB * TP1 * SDIM / 16) / 256, 256>>>(s_in);
    w1_transpose<<<dim3(HDIM / 32, SDIM / 32), dim3(32, 8)>>>(W1);
    traj_main<<<GRID, THREADS, SMEM_BYTES>>>(lengths, b1, W2);
    traj_post<<<BB, 256>>>(actions, lengths, b2);
    traj_reduce<<<1, BB>>>(out);
}

// round 17
// speedup vs baseline: 1.2795x; 1.2795x over previous
#include <cuda_runtime.h>
#include <cuda_bf16.h>
#include <cuda_fp8.h>
#include <math.h>
#include <stdint.h>

// Problem constants
#define BB    64
#define MAXT  511
#define TP1   512
#define SDIM  1024
#define HDIM  4096

// Tiling (fp8: KC = 128 k-elements = 128 bytes per row-chunk)
#define MT       64                   // rows per item
#define TILES_PER_B 8
#define KC       128
#define NCHUNK   (SDIM/KC)            // 8 chunks per item
#define NT       128                  // H cols per item
#define NNT      (HDIM/NT)            // 32
#define NITEMS   (NNT*BB*TILES_PER_B) // 16384 items: (nt, b, tile) nt-major
#define THREADS  128                  // 4 warps: 2 warp_m x 2 warp_n, each 32x64
#define GRID     592                  // persistent CTAs (4/SM)

// SMEM layout (bytes)
#define A_OFF(s)  ((s)*8192)              // 2 x 8 KB  (64 rows x 128B)
#define B_OFF(s)  (16384 + (s)*16384)     // 2 x 16 KB (128 rows x 128B)
#define LOG_OFF   49152                   // 64*4 floats = 1 KB
#define ITEM_OFF  50176
#define SMEM_BYTES 50304

#define SW128(x) ((x) ^ (((x) >> 3) & 0x70))

__device__ uint8_t g_sbf[(size_t)BB * TP1 * SDIM];   // 33.5 MB: s in e4m3
__device__ uint8_t g_w1t[(size_t)HDIM * SDIM];       // 4 MB  : W1^T e4m3
__device__ float   g_logits[(size_t)BB * TP1 * 4];   // 512 KB partial logits
__device__ float   g_post[BB];
__device__ unsigned g_counter;

// ---------------- helpers ----------------
__device__ __forceinline__ uint32_t smem_u32(const void* p) {
    uint32_t a;
    asm("{ .reg .u64 t; cvta.to.shared.u64 t, %1; cvt.u32.u64 %0, t; }" : "=r"(a) : "l"(p));
    return a;
}
__device__ __forceinline__ uint32_t fp8x4(float a, float b, float c, float d) {
    __nv_fp8x2_storage_t lo = __nv_cvt_float2_to_fp8x2(make_float2(a, b),
                                                       __NV_SATFINITE, __NV_E4M3);
    __nv_fp8x2_storage_t hi = __nv_cvt_float2_to_fp8x2(make_float2(c, d),
                                                       __NV_SATFINITE, __NV_E4M3);
    return (uint32_t)lo | ((uint32_t)hi << 16);
}
__device__ __forceinline__ void cp16(uint32_t dst, const void* src) {
    asm volatile("cp.async.cg.shared.global [%0], [%1], 16;" :: "r"(dst), "l"(src));
}
__device__ __forceinline__ void ldsm_x4(uint32_t* r, uint32_t addr) {
    asm volatile("ldmatrix.sync.aligned.m8n8.x4.shared.b16 {%0,%1,%2,%3}, [%4];"
                 : "=r"(r[0]), "=r"(r[1]), "=r"(r[2]), "=r"(r[3]) : "r"(addr));
}
__device__ __forceinline__ void mma16832(float* d, const uint32_t* a,
                                         uint32_t b0, uint32_t b1) {
    asm volatile("mma.sync.aligned.m16n8k32.row.col.f32.e4m3.e4m3.f32 "
                 "{%0,%1,%2,%3}, {%4,%5,%6,%7}, {%8,%9}, {%0,%1,%2,%3};"
                 : "+f"(d[0]), "+f"(d[1]), "+f"(d[2]), "+f"(d[3])
                 : "r"(a[0]), "r"(a[1]), "r"(a[2]), "r"(a[3]), "r"(b0), "r"(b1));
}

// ---------------- prepass kernels ----------------
extern "C" __global__ void init_counter() { g_counter = 0u; }

extern "C" __global__ void zero_logits() {
    ((float4*)g_logits)[blockIdx.x * 256 + threadIdx.x] = make_float4(0.f, 0.f, 0.f, 0.f);
}

extern "C" __global__ void s_cvt(const float* __restrict__ s) {
    size_t i = (size_t)blockIdx.x * 256 + threadIdx.x;
    const float4* p = (const float4*)s + i * 4;
    float4 v0 = p[0], v1 = p[1], v2 = p[2], v3 = p[3];
    uint4 o;
    o.x = fp8x4(v0.x, v0.y, v0.z, v0.w);
    o.y = fp8x4(v1.x, v1.y, v1.z, v1.w);
    o.z = fp8x4(v2.x, v2.y, v2.z, v2.w);
    o.w = fp8x4(v3.x, v3.y, v3.z, v3.w);
    ((uint4*)g_sbf)[i] = o;
}

extern "C" __global__ void w1_transpose(const float* __restrict__ W1) {
    __shared__ float tile[32][33];
    int n0 = blockIdx.x * 32, k0 = blockIdx.y * 32;
    int tx = threadIdx.x, ty = threadIdx.y;
    #pragma unroll
    for (int i = 0; i < 32; i += 8)
        tile[ty + i][tx] = W1[(size_t)(k0 + ty + i) * HDIM + n0 + tx];
    __syncthreads();
    #pragma unroll
    for (int i = 0; i < 32; i += 8) {
        __nv_fp8_storage_t v = __nv_cvt_float_to_fp8(tile[tx][ty + i],
                                                     __NV_SATFINITE, __NV_E4M3);
        g_w1t[(size_t)(n0 + ty + i) * SDIM + k0 + tx] = (uint8_t)v;
    }
}

// ---------------- main persistent kernel ----------------
extern "C" __global__ void __launch_bounds__(THREADS, 4)
traj_main(const int* __restrict__ lengths, const float* __restrict__ b1,
          const float* __restrict__ W2)
{
    extern __shared__ __align__(1024) char smem[];
    float*    logitsS = (float*)(smem + LOG_OFF);
    unsigned* itemS   = (unsigned*)(smem + ITEM_OFF);
    const uint32_t smem_u = smem_u32(smem);

    const int tid  = threadIdx.x;
    const int lane = tid & 31;
    const int wid  = tid >> 5;
    const int warp_m = wid & 1;          // 2 row-groups of 32 (64 rows)
    const int warp_n = wid >> 1;         // 2 col-groups of 64 (128 cols)
    const int m0  = warp_m * 32;
    const int n0w = warp_n * 64;

    // Per-thread cp.async base (128 threads: rowT 0..15, kgT 0..7)
    // piece strides 16 rows = 2048B: swizzle-transparent (bits >= 11)
    const int rowT = tid >> 3, kgT = tid & 7;
    const int src0 = rowT * SDIM + kgT * 16;
    const uint32_t dst0 = SW128(rowT * 128 + kgT * 16);
    const uint32_t offA0 = SW128((m0 + (lane & 15)) * 128 + (lane >> 4) * 16);
    const uint32_t offB0 = SW128((n0w + (lane & 15)) * 128 + (lane >> 4) * 16);

    for (;;) {
        if (tid == 0) itemS[0] = atomicAdd(&g_counter, 1u);
        __syncthreads();
        const unsigned item = itemS[0];
        __syncthreads();
        if (item >= NITEMS) break;
        // nt in HIGH bits (R11-proven ordering)
        const int nt   = item >> 9;
        const int rem  = item & 511;
        const int b    = rem >> 3;
        const int tile = rem & 7;
        const int t_base = tile * MT;
        const int len = lengths[b];
        if (t_base >= len) continue;

        logitsS[tid] = 0.f;                // 64 rows x 4 actions = 256 floats
        logitsS[tid + 128] = 0.f;

        const uint8_t* abase = g_sbf + ((size_t)b * TP1 + t_base) * SDIM + src0;
        const uint8_t* bbase = g_w1t + (size_t)nt * NT * SDIM + src0;

        float d[2][8][4];
        #pragma unroll
        for (int mi = 0; mi < 2; ++mi)
            #pragma unroll
            for (int ni = 0; ni < 8; ++ni)
                #pragma unroll
                for (int k = 0; k < 4; ++k) d[mi][ni][k] = 0.f;

        // ---- preload chunk 0 (A: 4 pieces, B: 8 pieces per thread) ----
        #pragma unroll
        for (int i = 0; i < 4; ++i)
            cp16(smem_u + A_OFF(0) + dst0 + i * 2048, abase + i * 16 * SDIM);
        #pragma unroll
        for (int i = 0; i < 8; ++i)
            cp16(smem_u + B_OFF(0) + dst0 + i * 2048, bbase + i * 16 * SDIM);
        asm volatile("cp.async.commit_group;");

        for (int c = 0; c < NCHUNK; ++c) {
            if (c + 1 < NCHUNK) {      // prefetch BEFORE wait (R15-proven order)
                const int nb = (c + 1) & 1, koff = (c + 1) * KC;
                #pragma unroll
                for (int i = 0; i < 4; ++i)
                    cp16(smem_u + A_OFF(nb) + dst0 + i * 2048,
                         abase + koff + i * 16 * SDIM);
                #pragma unroll
                for (int i = 0; i < 8; ++i)
                    cp16(smem_u + B_OFF(nb) + dst0 + i * 2048,
                         bbase + koff + i * 16 * SDIM);
                asm volatile("cp.async.commit_group;");
                asm volatile("cp.async.wait_group 1;");
            } else {
                asm volatile("cp.async.wait_group 0;");
            }
            __syncthreads();

            const uint32_t aS = smem_u + A_OFF(c & 1);
            const uint32_t bS = smem_u + B_OFF(c & 1);

            // fragment-pipelined ks loop: bq double-buffered 1 ks ahead
            uint32_t bq0[4][4], bq1[4][4];
            {
                const uint32_t bB = bS + offB0;
                #pragma unroll
                for (int nj = 0; nj < 4; ++nj)
                    ldsm_x4(bq0[nj], bB + nj * 2048);
            }
            #pragma unroll
            for (int ks = 0; ks < 4; ++ks) {
                const uint32_t kx = (uint32_t)(ks << 5);
                uint32_t afr[2][4];
                {
                    const uint32_t aB = aS + (offA0 ^ kx);
                    #pragma unroll
                    for (int mi = 0; mi < 2; ++mi)
                        ldsm_x4(afr[mi], aB + mi * 2048);
                }
                uint32_t (*cur)[4] = (ks & 1) ? bq1 : bq0;
                uint32_t (*nxt)[4] = (ks & 1) ? bq0 : bq1;
                if (ks < 3) {
                    const uint32_t bB = bS + (offB0 ^ (uint32_t)((ks + 1) << 5));
                    #pragma unroll
                    for (int nj = 0; nj < 4; ++nj)
                        ldsm_x4(nxt[nj], bB + nj * 2048);
                }
                #pragma unroll
                for (int mi = 0; mi < 2; ++mi)
                    #pragma unroll
                    for (int nj = 0; nj < 4; ++nj) {
                        mma16832(d[mi][2*nj],   afr[mi], cur[nj][0], cur[nj][2]);
                        mma16832(d[mi][2*nj+1], afr[mi], cur[nj][1], cur[nj][3]);
                    }
            }
            __syncthreads();
        }

        // ---- fused epilogue: relu(acc+b1) . W2[:,0:4] ----
        float plog[4][4];
        #pragma unroll
        for (int i = 0; i < 4; ++i)
            #pragma unroll
            for (int a = 0; a < 4; ++a) plog[i][a] = 0.f;

        #pragma unroll
        for (int ni = 0; ni < 8; ++ni) {
            #pragma unroll
            for (int jc = 0; jc < 2; ++jc) {
                int col = nt * NT + n0w + ni * 8 + 2 * (lane & 3) + jc;
                float bias = __ldg(b1 + col);
                float4 w2v = *(const float4*)(W2 + (size_t)col * 32);
                #pragma unroll
                for (int mi = 0; mi < 2; ++mi) {
                    #pragma unroll
                    for (int half = 0; half < 2; ++half) {
                        float h = d[mi][ni][half * 2 + jc] + bias;
                        h = fmaxf(h, 0.f);
                        int slot = mi * 2 + half;
                        plog[slot][0] += h * w2v.x;
                        plog[slot][1] += h * w2v.y;
                        plog[slot][2] += h * w2v.z;
                        plog[slot][3] += h * w2v.w;
                    }
                }
            }
        }

        #pragma unroll
        for (int slot = 0; slot < 4; ++slot) {
            int row = m0 + (slot >> 1) * 16 + (slot & 1) * 8 + (lane >> 2);
            #pragma unroll
            for (int a = 0; a < 4; ++a)
                atomicAdd(&logitsS[row * 4 + a], plog[slot][a]);
        }
        __syncthreads();
        if (tid < MT) {
            float* gl = g_logits + ((size_t)b * TP1 + t_base + tid) * 4;
            #pragma unroll
            for (int a = 0; a < 4; ++a)
                atomicAdd(gl + a, logitsS[tid * 4 + a]);
        }
    }
}

// ---------------- post: softmax + gather + masked sum per batch ----------------
extern "C" __global__ void traj_post(const int* __restrict__ actions,
                                     const int* __restrict__ lengths,
                                     const float* __restrict__ b2)
{
    const int b = blockIdx.x;
    const int tid = threadIdx.x;
    const int len = lengths[b];
    const float bb0 = b2[0], bb1 = b2[1], bb2 = b2[2], bb3 = b2[3];
    float acc = 0.f;
    for (int t = tid; t < len; t += 256) {
        const float4 z4 = *(const float4*)(g_logits + ((size_t)b * TP1 + t) * 4);
        float z[4] = { z4.x + bb0, z4.y + bb1, z4.z + bb2, z4.w + bb3 };
        float zm = fmaxf(fmaxf(z[0], z[1]), fmaxf(z[2], z[3]));
        float se = expf(z[0]-zm) + expf(z[1]-zm) + expf(z[2]-zm) + expf(z[3]-zm);
        float lse = zm + logf(se);
        int act = actions[b * MAXT + t];
        acc += z[act] - lse;
    }
    #pragma unroll
    for (int off = 16; off > 0; off >>= 1)
        acc += __shfl_xor_sync(0xffffffffu, acc, off);
    __shared__ float red[8];
    if ((tid & 31) == 0) red[tid >> 5] = acc;
    __syncthreads();
    if (tid == 0) {
        float s = 0.f;
        #pragma unroll
        for (int w = 0; w < 8; ++w) s += red[w];
        g_post[b] = s;
    }
}

extern "C" __global__ void traj_reduce(float* __restrict__ out)
{
    __shared__ float sm[BB];
    int i = threadIdx.x;
    sm[i] = g_post[i];
    __syncthreads();
    for (int off = BB / 2; off > 0; off >>= 1) {
        if (i < off) sm[i] += sm[i + off];
        __syncthreads();
    }
    if (i == 0) out[0] = -sm[0];
}

extern "C" void kernel_launch(void* const* d_in, const int* in_sizes, int n_in,
                              void* d_out, int out_size)
{
    const float* s_in    = (const float*)d_in[0];
    const int*   actions = (const int*)  d_in[1];
    const int*   lengths = (const int*)  d_in[2];
    const float* W1      = (const float*)d_in[3];
    const float* b1      = (const float*)d_in[4];
    const float* W2      = (const float*)d_in[5];
    const float* b2      = (const float*)d_in[6];
    float* out = (float*)d_out;

    cudaFuncSetAttribute(traj_main, cudaFuncAttributeMaxDynamicSharedMemorySize, SMEM_BYTES);

    init_counter<<<1, 1>>>();
    zero_logits<<<512, 256>>>();
    s_cvt<<<(BB * TP1 * SDIM / 16) / 256, 256>>>(s_in);
    w1_transpose<<<dim3(HDIM / 32, SDIM / 32), dim3(32, 8)>>>(W1);
    traj_main<<<GRID, THREADS, SMEM_BYTES>>>(lengths, b1, W2);
    traj_post<<<BB, 256>>>(actions, lengths, b2);
    traj_reduce<<<1, BB>>>(out);
}